// round 1
// baseline (speedup 1.0000x reference)
#include <cuda_runtime.h>
#include <math.h>
#include <stdint.h>

// ---------------- scratch (allocation-free: __device__ globals) ----------------
// hidden: [32768, 512] fp32 ; params: [32768, 1792] fp32
__device__ float g_hidden[32768ULL * 512];
__device__ float g_params[32768ULL * 1792];

#define BVAL   3.0f
#define KBINS  5
#define MIN_BW 0.001f
#define MIN_BH 0.001f
#define MIN_DV 0.001f

__device__ __forceinline__ float softplusf(float x) {
    return (x > 20.0f) ? x : log1pf(expf(x));
}

// ----------------------------------------------------------------------------
// C[N x M] = act(A[N x K] @ B[K x M] + bias)   (all row-major, fp32)
// BM=BN=128, BK=16, 256 threads, 8x8 micro-tile per thread.
// Inner product uses packed fma.rn.f32x2 (exact fp32 FMA semantics).
// Dims assumed multiples of tile sizes (true for this problem: K in {128,512},
// M in {512,1792}, N=32768).
// ----------------------------------------------------------------------------
template <int ACT>
__global__ void __launch_bounds__(256) gemm_bias_act(
    const float* __restrict__ A, int lda,
    const float* __restrict__ B,
    const float* __restrict__ bias,
    float* __restrict__ C, int M, int Kd)
{
    __shared__ float As[16][128];   // transposed A tile: As[k][row]
    __shared__ float Bs[16][128];   // Bs[k][col]

    const int tid = threadIdx.x;
    const int tx = tid & 15;        // 0..15 (column group)
    const int ty = tid >> 4;        // 0..15 (row group)
    const int rowBase = blockIdx.y * 128;
    const int colBase = blockIdx.x * 128;

    const float* Ag = A + (size_t)rowBase * lda;
    const float* Bg = B + colBase;

    unsigned long long acc[8][4];   // 8 rows x 4 packed col-pairs (= 8x8 fp32)
#pragma unroll
    for (int i = 0; i < 8; i++)
#pragma unroll
        for (int j = 0; j < 4; j++) acc[i][j] = 0ULL;

    const int arow = tid >> 2;          // 0..63
    const int acol = (tid & 3) << 2;    // 0,4,8,12
    const int brow = tid >> 5;          // 0..7
    const int bcol = (tid & 31) << 2;   // 0..124

    for (int kc = 0; kc < Kd; kc += 16) {
        // ---- load A tile (2 x float4 per thread), store transposed ----
        float4 a0 = *(const float4*)(Ag + (size_t)arow * lda + kc + acol);
        float4 a1 = *(const float4*)(Ag + (size_t)(arow + 64) * lda + kc + acol);
        As[acol + 0][arow] = a0.x; As[acol + 1][arow] = a0.y;
        As[acol + 2][arow] = a0.z; As[acol + 3][arow] = a0.w;
        As[acol + 0][arow + 64] = a1.x; As[acol + 1][arow + 64] = a1.y;
        As[acol + 2][arow + 64] = a1.z; As[acol + 3][arow + 64] = a1.w;

        // ---- load B tile (2 x float4 per thread) ----
        float4 b0 = *(const float4*)(Bg + (size_t)(kc + brow) * M + bcol);
        float4 b1 = *(const float4*)(Bg + (size_t)(kc + brow + 8) * M + bcol);
        *(float4*)&Bs[brow][bcol]     = b0;
        *(float4*)&Bs[brow + 8][bcol] = b1;

        __syncthreads();

#pragma unroll
        for (int k = 0; k < 16; k++) {
            float a[8];
            *(float4*)&a[0] = *(const float4*)&As[k][ty * 8];
            *(float4*)&a[4] = *(const float4*)&As[k][ty * 8 + 4];
            float4 bb0 = *(const float4*)&Bs[k][tx * 8];
            float4 bb1 = *(const float4*)&Bs[k][tx * 8 + 4];

            unsigned long long b2[4];
            asm("mov.b64 %0, {%1,%2};" : "=l"(b2[0]) : "f"(bb0.x), "f"(bb0.y));
            asm("mov.b64 %0, {%1,%2};" : "=l"(b2[1]) : "f"(bb0.z), "f"(bb0.w));
            asm("mov.b64 %0, {%1,%2};" : "=l"(b2[2]) : "f"(bb1.x), "f"(bb1.y));
            asm("mov.b64 %0, {%1,%2};" : "=l"(b2[3]) : "f"(bb1.z), "f"(bb1.w));

#pragma unroll
            for (int i = 0; i < 8; i++) {
                unsigned long long ad;
                asm("mov.b64 %0, {%1,%1};" : "=l"(ad) : "f"(a[i]));
#pragma unroll
                for (int j = 0; j < 4; j++) {
                    asm("fma.rn.f32x2 %0, %1, %2, %0;"
                        : "+l"(acc[i][j]) : "l"(ad), "l"(b2[j]));
                }
            }
        }
        __syncthreads();
    }

    // ---- epilogue: bias (+ optional tanh), store ----
    const int crow = rowBase + ty * 8;
    const int ccol = colBase + tx * 8;
#pragma unroll
    for (int i = 0; i < 8; i++) {
#pragma unroll
        for (int j = 0; j < 4; j++) {
            float v0 = __uint_as_float((unsigned)(acc[i][j] & 0xffffffffULL));
            float v1 = __uint_as_float((unsigned)(acc[i][j] >> 32));
            v0 += bias[ccol + j * 2];
            v1 += bias[ccol + j * 2 + 1];
            if (ACT == 1) { v0 = tanhf(v0); v1 = tanhf(v1); }
            float2 st = make_float2(v0, v1);
            *(float2*)&C[(size_t)(crow + i) * M + ccol + j * 2] = st;
        }
    }
}

// ----------------------------------------------------------------------------
// Rational-quadratic spline transform. One block per row, one thread per d2.
// Faithful to the reference: softmax(2B*softmax(raw)) for widths/heights,
// MIN_D + softplus(softplus(raw)) for interior derivatives, boundary deriv 1.
// ----------------------------------------------------------------------------
__global__ void __launch_bounds__(128) spline_kernel(
    const float* __restrict__ xin, int xoff,     // input value column offset (row stride 256)
    const float* __restrict__ params,            // [N, 1792]
    float* __restrict__ z, int zoff,             // output column offset (row stride 256)
    float* __restrict__ logdet, int add)
{
    const int n = blockIdx.x;
    const int d = threadIdx.x;   // 0..127

    const float* p = params + (size_t)n * 1792 + d * 14;
    float raw[14];
#pragma unroll
    for (int j = 0; j < 14; j++) raw[j] = p[j];

    const float t = xin[(size_t)n * 256 + xoff + d];

    // ---- widths / knot x-positions ----
    float cw[6], wd[5];
    {
        float m = raw[0];
#pragma unroll
        for (int j = 1; j < 5; j++) m = fmaxf(m, raw[j]);
        float e[5], s = 0.f;
#pragma unroll
        for (int j = 0; j < 5; j++) { e[j] = expf(raw[j] - m); s += e[j]; }
        float Wu[5];
#pragma unroll
        for (int j = 0; j < 5; j++) Wu[j] = 2.0f * BVAL * e[j] / s;
        float m2 = Wu[0];
#pragma unroll
        for (int j = 1; j < 5; j++) m2 = fmaxf(m2, Wu[j]);
        float e2[5], s2 = 0.f;
#pragma unroll
        for (int j = 0; j < 5; j++) { e2[j] = expf(Wu[j] - m2); s2 += e2[j]; }
        cw[0] = -BVAL;
        float run = 0.f;
#pragma unroll
        for (int j = 0; j < 5; j++) {
            float w = MIN_BW + (1.0f - MIN_BW * KBINS) * (e2[j] / s2);
            run += w;
            cw[j + 1] = 2.0f * BVAL * run - BVAL;
        }
        cw[5] = BVAL;
#pragma unroll
        for (int j = 0; j < 5; j++) wd[j] = cw[j + 1] - cw[j];
    }

    // ---- heights / knot y-positions ----
    float ch[6], hd[5];
    {
        float m = raw[5];
#pragma unroll
        for (int j = 1; j < 5; j++) m = fmaxf(m, raw[5 + j]);
        float e[5], s = 0.f;
#pragma unroll
        for (int j = 0; j < 5; j++) { e[j] = expf(raw[5 + j] - m); s += e[j]; }
        float Hu[5];
#pragma unroll
        for (int j = 0; j < 5; j++) Hu[j] = 2.0f * BVAL * e[j] / s;
        float m2 = Hu[0];
#pragma unroll
        for (int j = 1; j < 5; j++) m2 = fmaxf(m2, Hu[j]);
        float e2[5], s2 = 0.f;
#pragma unroll
        for (int j = 0; j < 5; j++) { e2[j] = expf(Hu[j] - m2); s2 += e2[j]; }
        ch[0] = -BVAL;
        float run = 0.f;
#pragma unroll
        for (int j = 0; j < 5; j++) {
            float h = MIN_BH + (1.0f - MIN_BH * KBINS) * (e2[j] / s2);
            run += h;
            ch[j + 1] = 2.0f * BVAL * run - BVAL;
        }
        ch[5] = BVAL;
#pragma unroll
        for (int j = 0; j < 5; j++) hd[j] = ch[j + 1] - ch[j];
    }

    // ---- derivatives at knots ----
    float deriv[6];
    deriv[0] = 1.0f;   // MIN_D + softplus(log(exp(1-MIN_D)-1)) == 1 exactly
    deriv[5] = 1.0f;
#pragma unroll
    for (int j = 0; j < 4; j++) {
        float du = softplusf(raw[10 + j]);          // _cond's softplus
        deriv[j + 1] = MIN_DV + softplusf(du);      // rqs's softplus
    }

    // ---- bin search + spline evaluation ----
    const float xc = fminf(fmaxf(t, -BVAL), BVAL);
    int cnt = 0;
#pragma unroll
    for (int j = 0; j < 6; j++) cnt += (xc >= cw[j]) ? 1 : 0;
    int idx = min(max(cnt - 1, 0), 4);

    const float icw = cw[idx], iw = wd[idx];
    const float ich = ch[idx], ih = hd[idx];
    const float delta = ih / iw;
    const float dk = deriv[idx], dk1 = deriv[idx + 1];
    const float theta = (xc - icw) / iw;
    const float t1m = theta * (1.0f - theta);
    const float num = ih * (delta * theta * theta + dk * t1m);
    const float den = delta + (dk + dk1 - 2.0f * delta) * t1m;
    const float y = ich + num / den;
    const float omt = 1.0f - theta;
    const float dnum = delta * delta * (dk1 * theta * theta + 2.0f * delta * t1m + dk * omt * omt);
    const float ld = logf(dnum) - 2.0f * logf(den);

    const bool inside = (t >= -BVAL) && (t <= BVAL);
    const float outv = inside ? y : t;
    const float ldv  = inside ? ld : 0.0f;

    z[(size_t)n * 256 + zoff + d] = outv;

    // ---- block reduction of log-det ----
    __shared__ float red[128];
    red[d] = ldv;
    __syncthreads();
#pragma unroll
    for (int s = 64; s > 0; s >>= 1) {
        if (d < s) red[d] += red[d + s];
        __syncthreads();
    }
    if (d == 0) {
        if (add) logdet[n] += red[0];
        else     logdet[n]  = red[0];
    }
}

// ----------------------------------------------------------------------------
extern "C" void kernel_launch(void* const* d_in, const int* in_sizes, int n_in,
                              void* d_out, int out_size)
{
    const float* x     = (const float*)d_in[0];   // [N, 256]
    const float* f0_w0 = (const float*)d_in[1];   // [128, 512]
    const float* f0_b0 = (const float*)d_in[2];   // [512]
    const float* f0_w1 = (const float*)d_in[3];   // [512, 1792]
    const float* f0_b1 = (const float*)d_in[4];   // [1792]
    const float* f1_w0 = (const float*)d_in[5];
    const float* f1_b0 = (const float*)d_in[6];
    const float* f1_w1 = (const float*)d_in[7];
    const float* f1_b1 = (const float*)d_in[8];

    const int N = in_sizes[0] / 256;              // 32768
    float* z      = (float*)d_out;                // [N, 256]
    float* logdet = z + (size_t)N * 256;          // [N]

    float* hidden = nullptr;
    float* params = nullptr;
    cudaGetSymbolAddress((void**)&hidden, g_hidden);
    cudaGetSymbolAddress((void**)&params, g_params);

    dim3 blk(256);
    dim3 g1(512 / 128, N / 128);    // (4, 256)
    dim3 g2(1792 / 128, N / 128);   // (14, 256)

    // ---- coupling 1: condition on x0 (cols 0..127), transform x1 (cols 128..255) ----
    gemm_bias_act<1><<<g1, blk>>>(x, 256, f0_w0, f0_b0, hidden, 512, 128);
    gemm_bias_act<0><<<g2, blk>>>(hidden, 512, f0_w1, f0_b1, params, 1792, 512);
    spline_kernel<<<N, 128>>>(x, 128, params, z, 128, logdet, 0);

    // ---- coupling 2: condition on new x1 (z cols 128..255), transform x0 ----
    gemm_bias_act<1><<<g1, blk>>>(z + 128, 256, f1_w0, f1_b0, hidden, 512, 128);
    gemm_bias_act<0><<<g2, blk>>>(hidden, 512, f1_w1, f1_b1, params, 1792, 512);
    spline_kernel<<<N, 128>>>(x, 0, params, z, 0, logdet, 1);
}